// round 1
// baseline (speedup 1.0000x reference)
#include <cuda_runtime.h>

// LightGCN: 3-layer propagation, CSR pull-based (no float atomics).
//   x = concat(user_emb, movie_emb)                  [N, 64]
//   deg[c] = #edges with col==c;  dis = deg>0 ? rsqrt(deg) : 0
//   norm_e = dis[row_e] * dis[col_e]
//   acc_{k+1}[c] = sum_{e: col_e==c} norm_e * acc_k[row_e]
//   out = (x + acc_1 + acc_2 + acc_3) / 4

#define NU 100000
#define NM 50000
#define NN 150000            // NU + NM
#define DIM 64
#define NE 5000000
#define NB_SCAN ((NN + 1023) / 1024)   // 147

// ---------------- scratch (static device globals; no allocations) ----------
__device__ int    g_is64;              // 1 if edge_index is int64, 0 if int32
__device__ int    g_deg[NN];
__device__ int    g_cur[NN];
__device__ int    g_off[NN + 1];
__device__ float  g_dis[NN];
__device__ int    g_scan[NN];
__device__ int    g_bsum[NB_SCAN];
__device__ int    g_bpre[NB_SCAN];
__device__ int2   g_edge[NE];          // packed (src, __float_as_int(norm))
__device__ float4 g_acc0[NN * DIM / 4];
__device__ float4 g_acc1[NN * DIM / 4];
__device__ float4 g_tot [NN * DIM / 4];

// ---------------- dtype detection ------------------------------------------
// If the buffer is really int32, interpreting pairs as int64 yields values
// >= 2^32 whenever the high word is nonzero (prob ~1 - (1/150000)^64).
__global__ void k_detect(const long long* __restrict__ e) {
    if (threadIdx.x == 0 && blockIdx.x == 0) {
        int is64 = 1;
        #pragma unroll 1
        for (int i = 0; i < 64; i++) {
            long long v = e[i];
            if (v < 0 || v >= (long long)NN) { is64 = 0; break; }
        }
        g_is64 = is64;
    }
}

__device__ __forceinline__ int edge_val(const void* eidx, long long idx, int is64) {
    if (is64) return (int)((const long long*)eidx)[idx];
    return ((const int*)eidx)[idx];
}

// ---------------- preprocessing ---------------------------------------------
__global__ void k_zero() {
    int i = blockIdx.x * blockDim.x + threadIdx.x;
    if (i < NN) { g_deg[i] = 0; g_cur[i] = 0; }
}

__global__ void k_count(const void* __restrict__ eidx, int E) {
    int is64 = g_is64;
    int stride = gridDim.x * blockDim.x;
    for (int e = blockIdx.x * blockDim.x + threadIdx.x; e < E; e += stride) {
        int c = edge_val(eidx, (long long)E + e, is64);
        atomicAdd(&g_deg[c], 1);
    }
}

// Hillis-Steele inclusive scan per 1024-block.
__global__ void k_scan1(int n) {
    __shared__ int sh[1024];
    int t = threadIdx.x;
    int i = blockIdx.x * 1024 + t;
    int v = (i < n) ? g_deg[i] : 0;
    sh[t] = v;
    __syncthreads();
    #pragma unroll
    for (int off = 1; off < 1024; off <<= 1) {
        int a = (t >= off) ? sh[t - off] : 0;
        __syncthreads();
        sh[t] += a;
        __syncthreads();
    }
    if (i < n) g_scan[i] = sh[t];
    if (t == 1023) g_bsum[blockIdx.x] = sh[t];
}

__global__ void k_scan2(int nb) {
    if (threadIdx.x == 0 && blockIdx.x == 0) {
        int s = 0;
        for (int b = 0; b < nb; b++) { g_bpre[b] = s; s += g_bsum[b]; }
    }
}

__global__ void k_scan3(int n) {   // launched with blockDim=1024, same grid as scan1
    int i = blockIdx.x * 1024 + threadIdx.x;
    if (i < n) {
        g_off[i + 1] = g_scan[i] + g_bpre[blockIdx.x];
        int d = g_deg[i];
        g_dis[i] = (d > 0) ? rsqrtf((float)d) : 0.0f;
        if (i == 0) g_off[0] = 0;
    }
}

__global__ void k_fill(const void* __restrict__ eidx, int E) {
    int is64 = g_is64;
    int stride = gridDim.x * blockDim.x;
    for (int e = blockIdx.x * blockDim.x + threadIdx.x; e < E; e += stride) {
        int r = edge_val(eidx, (long long)e, is64);
        int c = edge_val(eidx, (long long)E + e, is64);
        int pos = g_off[c] + atomicAdd(&g_cur[c], 1);
        float w = g_dis[r] * g_dis[c];
        g_edge[pos] = make_int2(r, __float_as_int(w));
    }
}

// ---------------- init: acc0 = tot = concat(user, movie) --------------------
__global__ void k_init(const float4* __restrict__ u, const float4* __restrict__ m,
                       int nu4, int nt4) {
    int stride = gridDim.x * blockDim.x;
    for (int i = blockIdx.x * blockDim.x + threadIdx.x; i < nt4; i += stride) {
        float4 v = (i < nu4) ? u[i] : m[i - nu4];
        g_acc0[i] = v;
        g_tot[i]  = v;
    }
}

// ---------------- propagation: one warp per target node ---------------------
__global__ void __launch_bounds__(256) k_prop(int layer) {
    const float2* __restrict__ in = (layer & 1) ? (const float2*)g_acc1
                                                : (const float2*)g_acc0;
    float2* __restrict__ out      = (layer & 1) ? (float2*)g_acc0
                                                : (float2*)g_acc1;
    int gw = (blockIdx.x * blockDim.x + threadIdx.x) >> 5;
    if (gw >= NN) return;
    int lane = threadIdx.x & 31;

    int i  = g_off[gw];
    int e1 = g_off[gw + 1];
    float sx = 0.0f, sy = 0.0f;

    for (; i + 4 <= e1; i += 4) {
        int2 ea = g_edge[i + 0];
        int2 eb = g_edge[i + 1];
        int2 ec = g_edge[i + 2];
        int2 ed = g_edge[i + 3];
        float2 va = __ldg(&in[ea.x * 32 + lane]);
        float2 vb = __ldg(&in[eb.x * 32 + lane]);
        float2 vc = __ldg(&in[ec.x * 32 + lane]);
        float2 vd = __ldg(&in[ed.x * 32 + lane]);
        float wa = __int_as_float(ea.y);
        float wb = __int_as_float(eb.y);
        float wc = __int_as_float(ec.y);
        float wd = __int_as_float(ed.y);
        sx += wa * va.x; sy += wa * va.y;
        sx += wb * vb.x; sy += wb * vb.y;
        sx += wc * vc.x; sy += wc * vc.y;
        sx += wd * vd.x; sy += wd * vd.y;
    }
    for (; i < e1; ++i) {
        int2 e = g_edge[i];
        float2 v = __ldg(&in[e.x * 32 + lane]);
        float w = __int_as_float(e.y);
        sx += w * v.x; sy += w * v.y;
    }

    int o = gw * 32 + lane;
    out[o] = make_float2(sx, sy);
    float2* tot = (float2*)g_tot;
    float2 t = tot[o];
    t.x += sx; t.y += sy;
    tot[o] = t;
}

// ---------------- finalize: d_out = tot / 4 ---------------------------------
__global__ void k_final(float4* __restrict__ outp, int n4) {
    int stride = gridDim.x * blockDim.x;
    for (int i = blockIdx.x * blockDim.x + threadIdx.x; i < n4; i += stride) {
        float4 t = g_tot[i];
        outp[i] = make_float4(0.25f * t.x, 0.25f * t.y, 0.25f * t.z, 0.25f * t.w);
    }
}

// ---------------- launch -----------------------------------------------------
extern "C" void kernel_launch(void* const* d_in, const int* in_sizes, int n_in,
                              void* d_out, int out_size) {
    // Locate inputs by element count (robust to ordering / n_layers scalar).
    int ie = 0, iu = 2, im = 3;
    for (int i = 0; i < n_in; i++) {
        if (in_sizes[i] == 2 * NE)      ie = i;
        else if (in_sizes[i] == NU * DIM) iu = i;
        else if (in_sizes[i] == NM * DIM) im = i;
    }
    const void*  eidx = d_in[ie];
    const float* uemb = (const float*)d_in[iu];
    const float* memb = (const float*)d_in[im];
    const int E = in_sizes[ie] / 2;

    k_detect<<<1, 32>>>((const long long*)eidx);
    k_zero<<<(NN + 255) / 256, 256>>>();
    k_count<<<2048, 256>>>(eidx, E);
    k_scan1<<<NB_SCAN, 1024>>>(NN);
    k_scan2<<<1, 32>>>(NB_SCAN);
    k_scan3<<<NB_SCAN, 1024>>>(NN);
    k_fill<<<2048, 256>>>(eidx, E);
    k_init<<<2048, 256>>>((const float4*)uemb, (const float4*)memb,
                          NU * DIM / 4, NN * DIM / 4);
    for (int l = 0; l < 3; l++) {
        k_prop<<<(NN * 32 + 255) / 256, 256>>>(l);
    }
    k_final<<<2048, 256>>>((float4*)d_out, NN * DIM / 4);
}